// round 14
// baseline (speedup 1.0000x reference)
#include <cuda_runtime.h>
#include <cuda_bf16.h>
#include <float.h>

#define NNODES 100000
#define F_IN   128
#define D1     256      // 8 heads * 32
#define HEADS  8
#define NCLS   40
#define NEG    0.2f
#define EMAX   1600000
#define SCAN_B 1024

// ---------------- scratch (device globals; no allocation allowed) ----------
__device__ __align__(16) float g_h1[NNODES * D1];              // x @ W1 (fp32)
__device__ __align__(16) __nv_bfloat16 g_h1b[NNODES * D1];     // bf16 copy for gather
__device__ __align__(16) __nv_bfloat16 g_h2b[NNODES * D1];     // layer-1 output (bf16)
__device__ float g_ssrc1[NNODES * HEADS];
__device__ float g_sdst1[NNODES * HEADS];
__device__ float g_pself1[NNODES * HEADS];
__device__ __align__(16) float g_h3[NNODES * NCLS];            // h2 @ W2 (fp32)
__device__ __align__(16) __nv_bfloat16 g_h3b[NNODES * NCLS];   // bf16 copy for gather
__device__ float g_ssrc2[NNODES];
__device__ float g_sdst2[NNODES];
__device__ float g_pself2[NNODES];
// CSR (dst-binned edges)
__device__ int g_counts[NNODES];
__device__ int g_rowptr[NNODES + 1];
__device__ int g_cursor[NNODES];
__device__ int g_csr_src[EMAX];
__device__ int g_bsum[(NNODES + SCAN_B - 1) / SCAN_B];
__device__ int g_boff[(NNODES + SCAN_B - 1) / SCAN_B];

__device__ __forceinline__ float lrelu(float v) { return v >= 0.f ? v : NEG * v; }
__device__ __forceinline__ unsigned f2tf32(float f) {
    unsigned u;
    asm("cvt.rna.tf32.f32 %0, %1;" : "=r"(u) : "f"(f));
    return u;
}

// ======================= CSR build ==========================================
__global__ __launch_bounds__(256) void zero_counts_kernel(int n) {
    int i = blockIdx.x * blockDim.x + threadIdx.x;
    if (i < n) g_counts[i] = 0;
}

__global__ __launch_bounds__(256) void hist_kernel(const int* __restrict__ dst, int E) {
    int e = blockIdx.x * blockDim.x + threadIdx.x;
    if (e < E) atomicAdd(&g_counts[dst[e]], 1);
}

__global__ __launch_bounds__(SCAN_B) void scan_sums_kernel(int n) {
    __shared__ int ws[32];
    int i = blockIdx.x * SCAN_B + threadIdx.x;
    int v = (i < n) ? g_counts[i] : 0;
    int lane = threadIdx.x & 31, w = threadIdx.x >> 5;
    int s = v;
#pragma unroll
    for (int o = 16; o; o >>= 1) s += __shfl_xor_sync(0xffffffffu, s, o);
    if (lane == 0) ws[w] = s;
    __syncthreads();
    if (w == 0) {
        int t = ws[lane];
#pragma unroll
        for (int o = 16; o; o >>= 1) t += __shfl_xor_sync(0xffffffffu, t, o);
        if (lane == 0) g_bsum[blockIdx.x] = t;
    }
}

__global__ __launch_bounds__(SCAN_B) void scan_offsets_kernel(int nb, int n) {
    __shared__ int ws[32];
    int lane = threadIdx.x & 31, w = threadIdx.x >> 5;
    int v = (threadIdx.x < nb) ? g_bsum[threadIdx.x] : 0;
    int x = v;
#pragma unroll
    for (int o = 1; o < 32; o <<= 1) {
        int y = __shfl_up_sync(0xffffffffu, x, o);
        if (lane >= o) x += y;
    }
    if (lane == 31) ws[w] = x;
    __syncthreads();
    if (w == 0) {
        int s = ws[lane];
#pragma unroll
        for (int o = 1; o < 32; o <<= 1) {
            int y = __shfl_up_sync(0xffffffffu, s, o);
            if (lane >= o) s += y;
        }
        ws[lane] = s;
    }
    __syncthreads();
    int incl = x + (w > 0 ? ws[w - 1] : 0);
    if (threadIdx.x < nb) g_boff[threadIdx.x] = incl - v;
    if (threadIdx.x == nb - 1) g_rowptr[n] = incl;
}

__global__ __launch_bounds__(SCAN_B) void scan_apply_kernel(int n) {
    __shared__ int ws[32];
    int i = blockIdx.x * SCAN_B + threadIdx.x;
    int v = (i < n) ? g_counts[i] : 0;
    int lane = threadIdx.x & 31, w = threadIdx.x >> 5;
    int x = v;
#pragma unroll
    for (int o = 1; o < 32; o <<= 1) {
        int y = __shfl_up_sync(0xffffffffu, x, o);
        if (lane >= o) x += y;
    }
    if (lane == 31) ws[w] = x;
    __syncthreads();
    if (w == 0) {
        int s = ws[lane];
#pragma unroll
        for (int o = 1; o < 32; o <<= 1) {
            int y = __shfl_up_sync(0xffffffffu, s, o);
            if (lane >= o) s += y;
        }
        ws[lane] = s;
    }
    __syncthreads();
    int excl = x - v + (w > 0 ? ws[w - 1] : 0) + g_boff[blockIdx.x];
    if (i < n) { g_rowptr[i] = excl; g_cursor[i] = excl; }
}

__global__ __launch_bounds__(256) void scatter_kernel(const int* __restrict__ src,
                                                      const int* __restrict__ dst, int E) {
    int e = blockIdx.x * blockDim.x + threadIdx.x;
    if (e >= E) return;
    int pos = atomicAdd(&g_cursor[dst[e]], 1);
    g_csr_src[pos] = src[e];
}

// ======== GEMM1 tf32 mma + fused scores + bf16 copy =========================
// Block 64x64; block's 64 cols = heads 2*bx, 2*bx+1 -> scores reduce in-block.
__global__ __launch_bounds__(256) void gemm1_tf32_kernel(const float* __restrict__ A,
                                                         const float* __restrict__ B,
                                                         const float* __restrict__ asrc,
                                                         const float* __restrict__ adst,
                                                         int M) {
    __shared__ unsigned As[64][36];
    __shared__ unsigned Bs[128][72];
    __shared__ float sS[64][2];
    __shared__ float sD[64][2];
    int tid = threadIdx.x;
    int warp = tid >> 5, lane = tid & 31;
    int q = lane >> 2, r4 = lane & 3;
    int rowBase = blockIdx.y * 64;
    int colBase = blockIdx.x * 64;
    int wm = (warp >> 2) * 32;
    int wn = (warp & 3) * 16;

    if (tid < 128) { sS[tid >> 1][tid & 1] = 0.f; sD[tid >> 1][tid & 1] = 0.f; }

    for (int j = tid; j < 2048; j += 256) {
        int k = j >> 4;
        int n4 = (j & 15) * 4;
        float4 v = *(const float4*)&B[(size_t)k * D1 + colBase + n4];
        uint4 t;
        t.x = f2tf32(v.x); t.y = f2tf32(v.y); t.z = f2tf32(v.z); t.w = f2tf32(v.w);
        *(uint4*)&Bs[k][n4] = t;
    }

    float c[2][2][4] = {};
    for (int kc = 0; kc < 4; kc++) {
        for (int j = tid; j < 512; j += 256) {
            int r = j >> 3;
            int k4 = (j & 7) * 4;
            int gr = rowBase + r;
            float4 v = make_float4(0.f, 0.f, 0.f, 0.f);
            if (gr < M) v = *(const float4*)&A[(size_t)gr * F_IN + kc * 32 + k4];
            uint4 t;
            t.x = f2tf32(v.x); t.y = f2tf32(v.y); t.z = f2tf32(v.z); t.w = f2tf32(v.w);
            *(uint4*)&As[r][k4] = t;
        }
        __syncthreads();
#pragma unroll
        for (int ks = 0; ks < 4; ks++) {
            int kk = ks * 8;
            unsigned a[2][4], b[2][2];
#pragma unroll
            for (int mt = 0; mt < 2; mt++) {
                int rr = wm + mt * 16 + q;
                a[mt][0] = As[rr][kk + r4];
                a[mt][1] = As[rr + 8][kk + r4];
                a[mt][2] = As[rr][kk + r4 + 4];
                a[mt][3] = As[rr + 8][kk + r4 + 4];
            }
#pragma unroll
            for (int nt = 0; nt < 2; nt++) {
                int cc = wn + nt * 8 + q;
                b[nt][0] = Bs[kc * 32 + kk + r4][cc];
                b[nt][1] = Bs[kc * 32 + kk + r4 + 4][cc];
            }
#pragma unroll
            for (int mt = 0; mt < 2; mt++)
#pragma unroll
                for (int nt = 0; nt < 2; nt++) {
                    asm volatile(
                        "mma.sync.aligned.m16n8k8.row.col.f32.tf32.tf32.f32 "
                        "{%0,%1,%2,%3}, {%4,%5,%6,%7}, {%8,%9}, {%0,%1,%2,%3};"
                        : "+f"(c[mt][nt][0]), "+f"(c[mt][nt][1]),
                          "+f"(c[mt][nt][2]), "+f"(c[mt][nt][3])
                        : "r"(a[mt][0]), "r"(a[mt][1]), "r"(a[mt][2]), "r"(a[mt][3]),
                          "r"(b[nt][0]), "r"(b[nt][1]));
                }
        }
        __syncthreads();
    }
    // Epilogue: write h1 fp32 + bf16 copy, accumulate scores in smem.
#pragma unroll
    for (int mt = 0; mt < 2; mt++) {
        int rl0 = wm + mt * 16 + q;
#pragma unroll
        for (int nt = 0; nt < 2; nt++) {
            int cb = wn + nt * 8 + r4 * 2;       // col within block
            int col = colBase + cb;
            int hh = cb >> 5;                    // head within block (0/1)
            float2 av = *(const float2*)&asrc[col];
            float2 dv = *(const float2*)&adst[col];
            int r0 = rowBase + rl0;
            if (r0 < M) {
                float2 w0 = make_float2(c[mt][nt][0], c[mt][nt][1]);
                *(float2*)&g_h1[(size_t)r0 * D1 + col] = w0;
                __nv_bfloat162 pb = __floats2bfloat162_rn(w0.x, w0.y);
                *(unsigned*)&g_h1b[(size_t)r0 * D1 + col] = *reinterpret_cast<unsigned*>(&pb);
                atomicAdd(&sS[rl0][hh], w0.x * av.x + w0.y * av.y);
                atomicAdd(&sD[rl0][hh], w0.x * dv.x + w0.y * dv.y);
            }
            if (r0 + 8 < M) {
                float2 w1 = make_float2(c[mt][nt][2], c[mt][nt][3]);
                *(float2*)&g_h1[(size_t)(r0 + 8) * D1 + col] = w1;
                __nv_bfloat162 pb = __floats2bfloat162_rn(w1.x, w1.y);
                *(unsigned*)&g_h1b[(size_t)(r0 + 8) * D1 + col] = *reinterpret_cast<unsigned*>(&pb);
                atomicAdd(&sS[rl0 + 8][hh], w1.x * av.x + w1.y * av.y);
                atomicAdd(&sD[rl0 + 8][hh], w1.x * dv.x + w1.y * dv.y);
            }
        }
    }
    __syncthreads();
    if (tid < 128) {
        int row = tid >> 1, h2i = tid & 1;
        int gr = rowBase + row;
        if (gr < M) {
            int head = blockIdx.x * 2 + h2i;
            float ps = sS[row][h2i], pd = sD[row][h2i];
            g_ssrc1[gr * HEADS + head] = ps;
            g_sdst1[gr * HEADS + head] = pd;
            g_pself1[gr * HEADS + head] = __expf(lrelu(ps + pd));
        }
    }
}

// ======== aggregate1: 1 warp/node, 8 ch/lane, bf16 gather, bf16 h2 out =====
__global__ __launch_bounds__(256) void aggregate1_kernel(const float* __restrict__ b1, int M) {
    int node = (blockIdx.x * blockDim.x + threadIdx.x) >> 5;
    int lane = threadIdx.x & 31;
    if (node >= M) return;
    int ch = lane * 8;
    int h  = lane >> 2;
    float sdst_h = g_sdst1[node * HEADS + h];
    float pself  = g_pself1[node * HEADS + h];
    size_t nb = (size_t)node * D1 + ch;
    float4 a0 = *(const float4*)&g_h1[nb];       // self term fp32
    float4 a1 = *(const float4*)&g_h1[nb + 4];
    float c0 = a0.x * pself, c1 = a0.y * pself, c2 = a0.z * pself, c3 = a0.w * pself;
    float c4 = a1.x * pself, c5 = a1.y * pself, c6 = a1.z * pself, c7 = a1.w * pself;
    float denom = pself;
    int beg = g_rowptr[node], end = g_rowptr[node + 1];
    int i = beg;
    for (; i + 4 <= end; i += 4) {
        int s0 = __ldg(&g_csr_src[i]);
        int s1 = __ldg(&g_csr_src[i + 1]);
        int s2 = __ldg(&g_csr_src[i + 2]);
        int s3 = __ldg(&g_csr_src[i + 3]);
        float e0 = __ldg(&g_ssrc1[s0 * HEADS + h]);
        float e1 = __ldg(&g_ssrc1[s1 * HEADS + h]);
        float e2 = __ldg(&g_ssrc1[s2 * HEADS + h]);
        float e3 = __ldg(&g_ssrc1[s3 * HEADS + h]);
        uint4 r0 = *(const uint4*)&g_h1b[(size_t)s0 * D1 + ch];
        uint4 r1 = *(const uint4*)&g_h1b[(size_t)s1 * D1 + ch];
        uint4 r2 = *(const uint4*)&g_h1b[(size_t)s2 * D1 + ch];
        uint4 r3 = *(const uint4*)&g_h1b[(size_t)s3 * D1 + ch];
        float p0 = __expf(lrelu(e0 + sdst_h));
        float p1 = __expf(lrelu(e1 + sdst_h));
        float p2 = __expf(lrelu(e2 + sdst_h));
        float p3 = __expf(lrelu(e3 + sdst_h));
        {
            float2 va = __bfloat1622float2(*reinterpret_cast<__nv_bfloat162*>(&r0.x));
            float2 vb = __bfloat1622float2(*reinterpret_cast<__nv_bfloat162*>(&r0.y));
            float2 vc = __bfloat1622float2(*reinterpret_cast<__nv_bfloat162*>(&r0.z));
            float2 vd = __bfloat1622float2(*reinterpret_cast<__nv_bfloat162*>(&r0.w));
            c0 += va.x * p0; c1 += va.y * p0; c2 += vb.x * p0; c3 += vb.y * p0;
            c4 += vc.x * p0; c5 += vc.y * p0; c6 += vd.x * p0; c7 += vd.y * p0;
        }
        {
            float2 va = __bfloat1622float2(*reinterpret_cast<__nv_bfloat162*>(&r1.x));
            float2 vb = __bfloat1622float2(*reinterpret_cast<__nv_bfloat162*>(&r1.y));
            float2 vc = __bfloat1622float2(*reinterpret_cast<__nv_bfloat162*>(&r1.z));
            float2 vd = __bfloat1622float2(*reinterpret_cast<__nv_bfloat162*>(&r1.w));
            c0 += va.x * p1; c1 += va.y * p1; c2 += vb.x * p1; c3 += vb.y * p1;
            c4 += vc.x * p1; c5 += vc.y * p1; c6 += vd.x * p1; c7 += vd.y * p1;
        }
        {
            float2 va = __bfloat1622float2(*reinterpret_cast<__nv_bfloat162*>(&r2.x));
            float2 vb = __bfloat1622float2(*reinterpret_cast<__nv_bfloat162*>(&r2.y));
            float2 vc = __bfloat1622float2(*reinterpret_cast<__nv_bfloat162*>(&r2.z));
            float2 vd = __bfloat1622float2(*reinterpret_cast<__nv_bfloat162*>(&r2.w));
            c0 += va.x * p2; c1 += va.y * p2; c2 += vb.x * p2; c3 += vb.y * p2;
            c4 += vc.x * p2; c5 += vc.y * p2; c6 += vd.x * p2; c7 += vd.y * p2;
        }
        {
            float2 va = __bfloat1622float2(*reinterpret_cast<__nv_bfloat162*>(&r3.x));
            float2 vb = __bfloat1622float2(*reinterpret_cast<__nv_bfloat162*>(&r3.y));
            float2 vc = __bfloat1622float2(*reinterpret_cast<__nv_bfloat162*>(&r3.z));
            float2 vd = __bfloat1622float2(*reinterpret_cast<__nv_bfloat162*>(&r3.w));
            c0 += va.x * p3; c1 += va.y * p3; c2 += vb.x * p3; c3 += vb.y * p3;
            c4 += vc.x * p3; c5 += vc.y * p3; c6 += vd.x * p3; c7 += vd.y * p3;
        }
        denom += (p0 + p1) + (p2 + p3);
    }
    for (; i < end; i++) {
        int s = __ldg(&g_csr_src[i]);
        float e = __ldg(&g_ssrc1[s * HEADS + h]);
        uint4 r = *(const uint4*)&g_h1b[(size_t)s * D1 + ch];
        float p = __expf(lrelu(e + sdst_h));
        float2 va = __bfloat1622float2(*reinterpret_cast<__nv_bfloat162*>(&r.x));
        float2 vb = __bfloat1622float2(*reinterpret_cast<__nv_bfloat162*>(&r.y));
        float2 vc = __bfloat1622float2(*reinterpret_cast<__nv_bfloat162*>(&r.z));
        float2 vd = __bfloat1622float2(*reinterpret_cast<__nv_bfloat162*>(&r.w));
        c0 += va.x * p; c1 += va.y * p; c2 += vb.x * p; c3 += vb.y * p;
        c4 += vc.x * p; c5 += vc.y * p; c6 += vd.x * p; c7 += vd.y * p;
        denom += p;
    }
    float inv = __frcp_rn(denom);
    float4 bb0 = *(const float4*)&b1[ch];
    float4 bb1 = *(const float4*)&b1[ch + 4];
    __nv_bfloat162 q0 = __floats2bfloat162_rn(fmaxf(c0 * inv + bb0.x, 0.f),
                                              fmaxf(c1 * inv + bb0.y, 0.f));
    __nv_bfloat162 q1 = __floats2bfloat162_rn(fmaxf(c2 * inv + bb0.z, 0.f),
                                              fmaxf(c3 * inv + bb0.w, 0.f));
    __nv_bfloat162 q2 = __floats2bfloat162_rn(fmaxf(c4 * inv + bb1.x, 0.f),
                                              fmaxf(c5 * inv + bb1.y, 0.f));
    __nv_bfloat162 q3 = __floats2bfloat162_rn(fmaxf(c6 * inv + bb1.z, 0.f),
                                              fmaxf(c7 * inv + bb1.w, 0.f));
    uint4 pk;
    pk.x = *reinterpret_cast<unsigned*>(&q0);
    pk.y = *reinterpret_cast<unsigned*>(&q1);
    pk.z = *reinterpret_cast<unsigned*>(&q2);
    pk.w = *reinterpret_cast<unsigned*>(&q3);
    *(uint4*)&g_h2b[nb] = pk;
}

// ======== GEMM2 via tf32 mma.sync (+ bf16 copy): h3 = h2b @ W2 =============
__global__ __launch_bounds__(256) void gemm2_tf32_kernel(const float* __restrict__ B, int M) {
    __shared__ unsigned As[128][36];
    __shared__ unsigned Bs[32][44];
    int tid = threadIdx.x;
    int warp = tid >> 5, lane = tid & 31;
    int q = lane >> 2, r4 = lane & 3;
    int rowBase = blockIdx.x * 128;
    int wm = warp * 16;

    float c[5][4] = {};
    for (int kc = 0; kc < 8; kc++) {
        // A chunk from bf16 h2: bf16<<16 is a valid tf32 bit pattern.
        for (int j = tid; j < 1024; j += 256) {
            int r = j >> 3;
            int k4 = (j & 7) * 4;
            int gr = rowBase + r;
            uint2 rv = make_uint2(0u, 0u);
            if (gr < M) rv = *(const uint2*)&g_h2b[(size_t)gr * D1 + kc * 32 + k4];
            uint4 t;
            t.x = rv.x << 16;
            t.y = rv.x & 0xffff0000u;
            t.z = rv.y << 16;
            t.w = rv.y & 0xffff0000u;
            *(uint4*)&As[r][k4] = t;
        }
        for (int j = tid; j < 1280; j += 256) {
            int k = j / NCLS;
            int n = j - k * NCLS;
            Bs[k][n] = f2tf32(B[(size_t)(kc * 32 + k) * NCLS + n]);
        }
        __syncthreads();
#pragma unroll
        for (int ks = 0; ks < 4; ks++) {
            int kk = ks * 8;
            unsigned a[4];
            int rr = wm + q;
            a[0] = As[rr][kk + r4];
            a[1] = As[rr + 8][kk + r4];
            a[2] = As[rr][kk + r4 + 4];
            a[3] = As[rr + 8][kk + r4 + 4];
#pragma unroll
            for (int nt = 0; nt < 5; nt++) {
                unsigned b0 = Bs[kk + r4][nt * 8 + q];
                unsigned b1 = Bs[kk + r4 + 4][nt * 8 + q];
                asm volatile(
                    "mma.sync.aligned.m16n8k8.row.col.f32.tf32.tf32.f32 "
                    "{%0,%1,%2,%3}, {%4,%5,%6,%7}, {%8,%9}, {%0,%1,%2,%3};"
                    : "+f"(c[nt][0]), "+f"(c[nt][1]), "+f"(c[nt][2]), "+f"(c[nt][3])
                    : "r"(a[0]), "r"(a[1]), "r"(a[2]), "r"(a[3]),
                      "r"(b0), "r"(b1));
            }
        }
        __syncthreads();
    }
    int r0 = rowBase + wm + q;
#pragma unroll
    for (int nt = 0; nt < 5; nt++) {
        int col = nt * 8 + r4 * 2;
        if (r0 < M) {
            float2 w0 = make_float2(c[nt][0], c[nt][1]);
            *(float2*)&g_h3[(size_t)r0 * NCLS + col] = w0;
            __nv_bfloat162 pb = __floats2bfloat162_rn(c[nt][0], c[nt][1]);
            *(unsigned*)&g_h3b[(size_t)r0 * NCLS + col] = *reinterpret_cast<unsigned*>(&pb);
        }
        if (r0 + 8 < M) {
            float2 w1 = make_float2(c[nt][2], c[nt][3]);
            *(float2*)&g_h3[(size_t)(r0 + 8) * NCLS + col] = w1;
            __nv_bfloat162 pb = __floats2bfloat162_rn(c[nt][2], c[nt][3]);
            *(unsigned*)&g_h3b[(size_t)(r0 + 8) * NCLS + col] = *reinterpret_cast<unsigned*>(&pb);
        }
    }
}

// ======== scores2: warp per node over h3 ====================================
__global__ __launch_bounds__(256) void scores2_kernel(const float* __restrict__ asrc,
                                                      const float* __restrict__ adst,
                                                      int n) {
    int wid  = (blockIdx.x * blockDim.x + threadIdx.x) >> 5;
    int lane = threadIdx.x & 31;
    if (wid >= n) return;
    size_t base = (size_t)wid * NCLS;
    float v0 = g_h3[base + lane];
    float v1 = (lane < 8) ? g_h3[base + 32 + lane] : 0.f;
    float a0 = asrc[lane], d0 = adst[lane];
    float a1 = (lane < 8) ? asrc[32 + lane] : 0.f;
    float d1 = (lane < 8) ? adst[32 + lane] : 0.f;
    float ps = v0 * a0 + v1 * a1;
    float pd = v0 * d0 + v1 * d1;
#pragma unroll
    for (int o = 16; o; o >>= 1) {
        ps += __shfl_xor_sync(0xffffffffu, ps, o);
        pd += __shfl_xor_sync(0xffffffffu, pd, o);
    }
    if (lane == 0) {
        g_ssrc2[wid] = ps;
        g_sdst2[wid] = pd;
        g_pself2[wid] = __expf(lrelu(ps + pd));
    }
}

// ======== aggregate2: warp/node, 2 ch/lane (lanes 0-19), bf16 gather ========
__global__ __launch_bounds__(256) void aggregate2_kernel(const float* __restrict__ b2,
                                                         float* __restrict__ out, int M) {
    int wid  = (blockIdx.x * blockDim.x + threadIdx.x) >> 5;
    int lane = threadIdx.x & 31;
    if (wid >= M) return;
    float sdst = g_sdst2[wid];
    float pself = g_pself2[wid];
    size_t nb = (size_t)wid * NCLS;
    bool act = lane < 20;
    int ch = lane * 2;
    float v0 = 0.f, v1 = 0.f;
    if (act) {
        float2 s = *(const float2*)&g_h3[nb + ch];
        v0 = s.x * pself; v1 = s.y * pself;
    }
    float denom = pself;
    int beg = g_rowptr[wid], end = g_rowptr[wid + 1];
    int i = beg;
    for (; i + 4 <= end; i += 4) {
        int s0 = __ldg(&g_csr_src[i]);
        int s1 = __ldg(&g_csr_src[i + 1]);
        int s2 = __ldg(&g_csr_src[i + 2]);
        int s3 = __ldg(&g_csr_src[i + 3]);
        float e0 = __ldg(&g_ssrc2[s0]);
        float e1 = __ldg(&g_ssrc2[s1]);
        float e2 = __ldg(&g_ssrc2[s2]);
        float e3 = __ldg(&g_ssrc2[s3]);
        unsigned r0 = 0, r1 = 0, r2 = 0, r3 = 0;
        if (act) {
            r0 = *(const unsigned*)&g_h3b[(size_t)s0 * NCLS + ch];
            r1 = *(const unsigned*)&g_h3b[(size_t)s1 * NCLS + ch];
            r2 = *(const unsigned*)&g_h3b[(size_t)s2 * NCLS + ch];
            r3 = *(const unsigned*)&g_h3b[(size_t)s3 * NCLS + ch];
        }
        float p0 = __expf(lrelu(e0 + sdst));
        float p1 = __expf(lrelu(e1 + sdst));
        float p2 = __expf(lrelu(e2 + sdst));
        float p3 = __expf(lrelu(e3 + sdst));
        float2 w0 = __bfloat1622float2(*reinterpret_cast<__nv_bfloat162*>(&r0));
        float2 w1 = __bfloat1622float2(*reinterpret_cast<__nv_bfloat162*>(&r1));
        float2 w2 = __bfloat1622float2(*reinterpret_cast<__nv_bfloat162*>(&r2));
        float2 w3 = __bfloat1622float2(*reinterpret_cast<__nv_bfloat162*>(&r3));
        v0 += w0.x * p0 + w1.x * p1 + w2.x * p2 + w3.x * p3;
        v1 += w0.y * p0 + w1.y * p1 + w2.y * p2 + w3.y * p3;
        denom += (p0 + p1) + (p2 + p3);
    }
    for (; i < end; i++) {
        int s = __ldg(&g_csr_src[i]);
        float e = __ldg(&g_ssrc2[s]);
        unsigned r = 0;
        if (act) r = *(const unsigned*)&g_h3b[(size_t)s * NCLS + ch];
        float p = __expf(lrelu(e + sdst));
        float2 w = __bfloat1622float2(*reinterpret_cast<__nv_bfloat162*>(&r));
        v0 += w.x * p; v1 += w.y * p;
        denom += p;
    }
    float inv = __frcp_rn(denom);
    float z0 = -FLT_MAX, z1 = -FLT_MAX;
    if (act) {
        z0 = v0 * inv + b2[ch];
        z1 = v1 * inv + b2[ch + 1];
    }
    float m = fmaxf(z0, z1);
#pragma unroll
    for (int o = 16; o; o >>= 1) m = fmaxf(m, __shfl_xor_sync(0xffffffffu, m, o));
    float s = act ? (expf(z0 - m) + expf(z1 - m)) : 0.f;
#pragma unroll
    for (int o = 16; o; o >>= 1) s += __shfl_xor_sync(0xffffffffu, s, o);
    float ls = logf(s);
    if (act) {
        out[nb + ch]     = z0 - m - ls;
        out[nb + ch + 1] = z1 - m - ls;
    }
}

// ---------------------------------------------------------------------------
extern "C" void kernel_launch(void* const* d_in, const int* in_sizes, int n_in,
                              void* d_out, int out_size) {
    const float* x     = (const float*)d_in[0];
    const int*   ei    = (const int*)d_in[1];      // JAX x64 disabled -> int32
    const float* W1    = (const float*)d_in[2];
    const float* asrc1 = (const float*)d_in[3];
    const float* adst1 = (const float*)d_in[4];
    const float* b1    = (const float*)d_in[5];
    const float* W2    = (const float*)d_in[6];
    const float* asrc2 = (const float*)d_in[7];
    const float* adst2 = (const float*)d_in[8];
    const float* b2    = (const float*)d_in[9];
    float* out = (float*)d_out;

    int M = in_sizes[0] / F_IN;        // 100000
    int E = in_sizes[1] / 2;           // 1600000
    const int* src = ei;
    const int* dst = ei + E;
    int NB = (M + SCAN_B - 1) / SCAN_B;

    static cudaStream_t s2 = nullptr;
    static cudaEvent_t evFork = nullptr, evJoin = nullptr;
    if (s2 == nullptr) {
        cudaStreamCreateWithFlags(&s2, cudaStreamNonBlocking);
        cudaEventCreateWithFlags(&evFork, cudaEventDisableTiming);
        cudaEventCreateWithFlags(&evJoin, cudaEventDisableTiming);
    }

    // Fork: CSR build on s2, GEMM1 (with fused scores) on main stream.
    cudaEventRecord(evFork, 0);
    cudaStreamWaitEvent(s2, evFork, 0);

    zero_counts_kernel<<<(M + 255) / 256, 256, 0, s2>>>(M);
    hist_kernel<<<(E + 255) / 256, 256, 0, s2>>>(dst, E);
    scan_sums_kernel<<<NB, SCAN_B, 0, s2>>>(M);
    scan_offsets_kernel<<<1, SCAN_B, 0, s2>>>(NB, M);
    scan_apply_kernel<<<NB, SCAN_B, 0, s2>>>(M);
    scatter_kernel<<<(E + 255) / 256, 256, 0, s2>>>(src, dst, E);
    cudaEventRecord(evJoin, s2);

    {
        dim3 grid(D1 / 64, (M + 63) / 64);
        gemm1_tf32_kernel<<<grid, 256>>>(x, W1, asrc1, adst1, M);
    }

    cudaStreamWaitEvent(0, evJoin, 0);

    aggregate1_kernel<<<(M * 32 + 255) / 256, 256>>>(b1, M);

    // Layer 2
    gemm2_tf32_kernel<<<(M + 127) / 128, 256>>>(W2, M);
    scores2_kernel<<<(M * 32 + 255) / 256, 256>>>(asrc2, adst2, M);
    aggregate2_kernel<<<(M * 32 + 255) / 256, 256>>>(b2, out, M);
}

// round 15
// speedup vs baseline: 1.0201x; 1.0201x over previous
#include <cuda_runtime.h>
#include <cuda_bf16.h>
#include <float.h>

#define NNODES 100000
#define F_IN   128
#define D1     256      // 8 heads * 32
#define HEADS  8
#define NCLS   40
#define NEG    0.2f
#define EMAX   1600000
#define SCAN_B 1024

// ---------------- scratch (device globals; no allocation allowed) ----------
__device__ __align__(16) __nv_bfloat16 g_h1b[NNODES * D1];     // x @ W1 (bf16)
__device__ __align__(16) __nv_bfloat16 g_h2b[NNODES * D1];     // layer-1 output (bf16)
__device__ float g_ssrc1[NNODES * HEADS];
__device__ float g_sdst1[NNODES * HEADS];
__device__ float g_pself1[NNODES * HEADS];
__device__ __align__(16) float g_h3[NNODES * NCLS];            // h2 @ W2 (fp32)
__device__ __align__(16) __nv_bfloat16 g_h3b[NNODES * NCLS];   // bf16 copy for gather
__device__ float g_ssrc2[NNODES];
__device__ float g_sdst2[NNODES];
__device__ float g_pself2[NNODES];
// CSR (dst-binned edges)
__device__ int g_counts[NNODES];
__device__ int g_rowptr[NNODES + 1];
__device__ int g_cursor[NNODES];
__device__ int g_csr_src[EMAX];
__device__ int g_bsum[(NNODES + SCAN_B - 1) / SCAN_B];
__device__ int g_boff[(NNODES + SCAN_B - 1) / SCAN_B];

__device__ __forceinline__ float lrelu(float v) { return v >= 0.f ? v : NEG * v; }
__device__ __forceinline__ unsigned f2tf32(float f) {
    unsigned u;
    asm("cvt.rna.tf32.f32 %0, %1;" : "=r"(u) : "f"(f));
    return u;
}

// ======================= CSR build ==========================================
__global__ __launch_bounds__(256) void zero_counts_kernel(int n) {
    int i = blockIdx.x * blockDim.x + threadIdx.x;
    if (i < n) g_counts[i] = 0;
}

__global__ __launch_bounds__(256) void hist_kernel(const int* __restrict__ dst, int E) {
    int e = blockIdx.x * blockDim.x + threadIdx.x;
    if (e < E) atomicAdd(&g_counts[dst[e]], 1);
}

__global__ __launch_bounds__(SCAN_B) void scan_sums_kernel(int n) {
    __shared__ int ws[32];
    int i = blockIdx.x * SCAN_B + threadIdx.x;
    int v = (i < n) ? g_counts[i] : 0;
    int lane = threadIdx.x & 31, w = threadIdx.x >> 5;
    int s = v;
#pragma unroll
    for (int o = 16; o; o >>= 1) s += __shfl_xor_sync(0xffffffffu, s, o);
    if (lane == 0) ws[w] = s;
    __syncthreads();
    if (w == 0) {
        int t = ws[lane];
#pragma unroll
        for (int o = 16; o; o >>= 1) t += __shfl_xor_sync(0xffffffffu, t, o);
        if (lane == 0) g_bsum[blockIdx.x] = t;
    }
}

__global__ __launch_bounds__(SCAN_B) void scan_offsets_kernel(int nb, int n) {
    __shared__ int ws[32];
    int lane = threadIdx.x & 31, w = threadIdx.x >> 5;
    int v = (threadIdx.x < nb) ? g_bsum[threadIdx.x] : 0;
    int x = v;
#pragma unroll
    for (int o = 1; o < 32; o <<= 1) {
        int y = __shfl_up_sync(0xffffffffu, x, o);
        if (lane >= o) x += y;
    }
    if (lane == 31) ws[w] = x;
    __syncthreads();
    if (w == 0) {
        int s = ws[lane];
#pragma unroll
        for (int o = 1; o < 32; o <<= 1) {
            int y = __shfl_up_sync(0xffffffffu, s, o);
            if (lane >= o) s += y;
        }
        ws[lane] = s;
    }
    __syncthreads();
    int incl = x + (w > 0 ? ws[w - 1] : 0);
    if (threadIdx.x < nb) g_boff[threadIdx.x] = incl - v;
    if (threadIdx.x == nb - 1) g_rowptr[n] = incl;
}

__global__ __launch_bounds__(SCAN_B) void scan_apply_kernel(int n) {
    __shared__ int ws[32];
    int i = blockIdx.x * SCAN_B + threadIdx.x;
    int v = (i < n) ? g_counts[i] : 0;
    int lane = threadIdx.x & 31, w = threadIdx.x >> 5;
    int x = v;
#pragma unroll
    for (int o = 1; o < 32; o <<= 1) {
        int y = __shfl_up_sync(0xffffffffu, x, o);
        if (lane >= o) x += y;
    }
    if (lane == 31) ws[w] = x;
    __syncthreads();
    if (w == 0) {
        int s = ws[lane];
#pragma unroll
        for (int o = 1; o < 32; o <<= 1) {
            int y = __shfl_up_sync(0xffffffffu, s, o);
            if (lane >= o) s += y;
        }
        ws[lane] = s;
    }
    __syncthreads();
    int excl = x - v + (w > 0 ? ws[w - 1] : 0) + g_boff[blockIdx.x];
    if (i < n) { g_rowptr[i] = excl; g_cursor[i] = excl; }
}

__global__ __launch_bounds__(256) void scatter_kernel(const int* __restrict__ src,
                                                      const int* __restrict__ dst, int E) {
    int e = blockIdx.x * blockDim.x + threadIdx.x;
    if (e >= E) return;
    int pos = atomicAdd(&g_cursor[dst[e]], 1);
    g_csr_src[pos] = src[e];
}

// ======== GEMM1 tf32 mma + fused scores + bf16 output only ==================
__global__ __launch_bounds__(256) void gemm1_tf32_kernel(const float* __restrict__ A,
                                                         const float* __restrict__ B,
                                                         const float* __restrict__ asrc,
                                                         const float* __restrict__ adst,
                                                         int M) {
    __shared__ unsigned As[64][36];
    __shared__ unsigned Bs[128][72];
    __shared__ float sS[64][2];
    __shared__ float sD[64][2];
    int tid = threadIdx.x;
    int warp = tid >> 5, lane = tid & 31;
    int q = lane >> 2, r4 = lane & 3;
    int rowBase = blockIdx.y * 64;
    int colBase = blockIdx.x * 64;
    int wm = (warp >> 2) * 32;
    int wn = (warp & 3) * 16;

    if (tid < 128) { sS[tid >> 1][tid & 1] = 0.f; sD[tid >> 1][tid & 1] = 0.f; }

    for (int j = tid; j < 2048; j += 256) {
        int k = j >> 4;
        int n4 = (j & 15) * 4;
        float4 v = *(const float4*)&B[(size_t)k * D1 + colBase + n4];
        uint4 t;
        t.x = f2tf32(v.x); t.y = f2tf32(v.y); t.z = f2tf32(v.z); t.w = f2tf32(v.w);
        *(uint4*)&Bs[k][n4] = t;
    }

    float c[2][2][4] = {};
    for (int kc = 0; kc < 4; kc++) {
        for (int j = tid; j < 512; j += 256) {
            int r = j >> 3;
            int k4 = (j & 7) * 4;
            int gr = rowBase + r;
            float4 v = make_float4(0.f, 0.f, 0.f, 0.f);
            if (gr < M) v = *(const float4*)&A[(size_t)gr * F_IN + kc * 32 + k4];
            uint4 t;
            t.x = f2tf32(v.x); t.y = f2tf32(v.y); t.z = f2tf32(v.z); t.w = f2tf32(v.w);
            *(uint4*)&As[r][k4] = t;
        }
        __syncthreads();
#pragma unroll
        for (int ks = 0; ks < 4; ks++) {
            int kk = ks * 8;
            unsigned a[2][4], b[2][2];
#pragma unroll
            for (int mt = 0; mt < 2; mt++) {
                int rr = wm + mt * 16 + q;
                a[mt][0] = As[rr][kk + r4];
                a[mt][1] = As[rr + 8][kk + r4];
                a[mt][2] = As[rr][kk + r4 + 4];
                a[mt][3] = As[rr + 8][kk + r4 + 4];
            }
#pragma unroll
            for (int nt = 0; nt < 2; nt++) {
                int cc = wn + nt * 8 + q;
                b[nt][0] = Bs[kc * 32 + kk + r4][cc];
                b[nt][1] = Bs[kc * 32 + kk + r4 + 4][cc];
            }
#pragma unroll
            for (int mt = 0; mt < 2; mt++)
#pragma unroll
                for (int nt = 0; nt < 2; nt++) {
                    asm volatile(
                        "mma.sync.aligned.m16n8k8.row.col.f32.tf32.tf32.f32 "
                        "{%0,%1,%2,%3}, {%4,%5,%6,%7}, {%8,%9}, {%0,%1,%2,%3};"
                        : "+f"(c[mt][nt][0]), "+f"(c[mt][nt][1]),
                          "+f"(c[mt][nt][2]), "+f"(c[mt][nt][3])
                        : "r"(a[mt][0]), "r"(a[mt][1]), "r"(a[mt][2]), "r"(a[mt][3]),
                          "r"(b[nt][0]), "r"(b[nt][1]));
                }
        }
        __syncthreads();
    }
    // Epilogue: bf16 h1 write + smem score accumulation.
#pragma unroll
    for (int mt = 0; mt < 2; mt++) {
        int rl0 = wm + mt * 16 + q;
#pragma unroll
        for (int nt = 0; nt < 2; nt++) {
            int cb = wn + nt * 8 + r4 * 2;
            int col = colBase + cb;
            int hh = cb >> 5;
            float2 av = *(const float2*)&asrc[col];
            float2 dv = *(const float2*)&adst[col];
            int r0 = rowBase + rl0;
            if (r0 < M) {
                float2 w0 = make_float2(c[mt][nt][0], c[mt][nt][1]);
                __nv_bfloat162 pb = __floats2bfloat162_rn(w0.x, w0.y);
                *(unsigned*)&g_h1b[(size_t)r0 * D1 + col] = *reinterpret_cast<unsigned*>(&pb);
                atomicAdd(&sS[rl0][hh], w0.x * av.x + w0.y * av.y);
                atomicAdd(&sD[rl0][hh], w0.x * dv.x + w0.y * dv.y);
            }
            if (r0 + 8 < M) {
                float2 w1 = make_float2(c[mt][nt][2], c[mt][nt][3]);
                __nv_bfloat162 pb = __floats2bfloat162_rn(w1.x, w1.y);
                *(unsigned*)&g_h1b[(size_t)(r0 + 8) * D1 + col] = *reinterpret_cast<unsigned*>(&pb);
                atomicAdd(&sS[rl0 + 8][hh], w1.x * av.x + w1.y * av.y);
                atomicAdd(&sD[rl0 + 8][hh], w1.x * dv.x + w1.y * dv.y);
            }
        }
    }
    __syncthreads();
    if (tid < 128) {
        int row = tid >> 1, h2i = tid & 1;
        int gr = rowBase + row;
        if (gr < M) {
            int head = blockIdx.x * 2 + h2i;
            float ps = sS[row][h2i], pd = sD[row][h2i];
            g_ssrc1[gr * HEADS + head] = ps;
            g_sdst1[gr * HEADS + head] = pd;
            g_pself1[gr * HEADS + head] = __expf(lrelu(ps + pd));
        }
    }
}

// ======== aggregate1: 1 warp/node, coop-index tiles, bf16 gather ============
__global__ __launch_bounds__(256) void aggregate1_kernel(const float* __restrict__ b1, int M) {
    int node = (blockIdx.x * blockDim.x + threadIdx.x) >> 5;
    int lane = threadIdx.x & 31;
    if (node >= M) return;
    int ch = lane * 8;
    int h  = lane >> 2;
    float sdst_h = g_sdst1[node * HEADS + h];
    float pself  = g_pself1[node * HEADS + h];
    size_t nb = (size_t)node * D1 + ch;
    uint4 sr = *(const uint4*)&g_h1b[nb];        // self term (bf16)
    float2 sa = __bfloat1622float2(*reinterpret_cast<__nv_bfloat162*>(&sr.x));
    float2 sb = __bfloat1622float2(*reinterpret_cast<__nv_bfloat162*>(&sr.y));
    float2 sc = __bfloat1622float2(*reinterpret_cast<__nv_bfloat162*>(&sr.z));
    float2 sd = __bfloat1622float2(*reinterpret_cast<__nv_bfloat162*>(&sr.w));
    float c0 = sa.x * pself, c1 = sa.y * pself, c2 = sb.x * pself, c3 = sb.y * pself;
    float c4 = sc.x * pself, c5 = sc.y * pself, c6 = sd.x * pself, c7 = sd.y * pself;
    float denom = pself;
    int beg = g_rowptr[node], end = g_rowptr[node + 1];

    for (int tile = beg; tile < end; tile += 32) {
        int n_t = end - tile;
        if (n_t > 32) n_t = 32;
        int myIdx = 0;
        if (tile + lane < end) myIdx = g_csr_src[tile + lane];   // coalesced
        int g = 0;
        for (; g + 4 <= n_t; g += 4) {
            int s0 = __shfl_sync(0xffffffffu, myIdx, g);
            int s1 = __shfl_sync(0xffffffffu, myIdx, g + 1);
            int s2 = __shfl_sync(0xffffffffu, myIdx, g + 2);
            int s3 = __shfl_sync(0xffffffffu, myIdx, g + 3);
            float e0 = __ldg(&g_ssrc1[s0 * HEADS + h]);
            float e1 = __ldg(&g_ssrc1[s1 * HEADS + h]);
            float e2 = __ldg(&g_ssrc1[s2 * HEADS + h]);
            float e3 = __ldg(&g_ssrc1[s3 * HEADS + h]);
            uint4 r0 = *(const uint4*)&g_h1b[(size_t)s0 * D1 + ch];
            uint4 r1 = *(const uint4*)&g_h1b[(size_t)s1 * D1 + ch];
            uint4 r2 = *(const uint4*)&g_h1b[(size_t)s2 * D1 + ch];
            uint4 r3 = *(const uint4*)&g_h1b[(size_t)s3 * D1 + ch];
            float p0 = __expf(lrelu(e0 + sdst_h));
            float p1 = __expf(lrelu(e1 + sdst_h));
            float p2 = __expf(lrelu(e2 + sdst_h));
            float p3 = __expf(lrelu(e3 + sdst_h));
            {
                float2 va = __bfloat1622float2(*reinterpret_cast<__nv_bfloat162*>(&r0.x));
                float2 vb = __bfloat1622float2(*reinterpret_cast<__nv_bfloat162*>(&r0.y));
                float2 vc = __bfloat1622float2(*reinterpret_cast<__nv_bfloat162*>(&r0.z));
                float2 vd = __bfloat1622float2(*reinterpret_cast<__nv_bfloat162*>(&r0.w));
                c0 += va.x * p0; c1 += va.y * p0; c2 += vb.x * p0; c3 += vb.y * p0;
                c4 += vc.x * p0; c5 += vc.y * p0; c6 += vd.x * p0; c7 += vd.y * p0;
            }
            {
                float2 va = __bfloat1622float2(*reinterpret_cast<__nv_bfloat162*>(&r1.x));
                float2 vb = __bfloat1622float2(*reinterpret_cast<__nv_bfloat162*>(&r1.y));
                float2 vc = __bfloat1622float2(*reinterpret_cast<__nv_bfloat162*>(&r1.z));
                float2 vd = __bfloat1622float2(*reinterpret_cast<__nv_bfloat162*>(&r1.w));
                c0 += va.x * p1; c1 += va.y * p1; c2 += vb.x * p1; c3 += vb.y * p1;
                c4 += vc.x * p1; c5 += vc.y * p1; c6 += vd.x * p1; c7 += vd.y * p1;
            }
            {
                float2 va = __bfloat1622float2(*reinterpret_cast<__nv_bfloat162*>(&r2.x));
                float2 vb = __bfloat1622float2(*reinterpret_cast<__nv_bfloat162*>(&r2.y));
                float2 vc = __bfloat1622float2(*reinterpret_cast<__nv_bfloat162*>(&r2.z));
                float2 vd = __bfloat1622float2(*reinterpret_cast<__nv_bfloat162*>(&r2.w));
                c0 += va.x * p2; c1 += va.y * p2; c2 += vb.x * p2; c3 += vb.y * p2;
                c4 += vc.x * p2; c5 += vc.y * p2; c6 += vd.x * p2; c7 += vd.y * p2;
            }
            {
                float2 va = __bfloat1622float2(*reinterpret_cast<__nv_bfloat162*>(&r3.x));
                float2 vb = __bfloat1622float2(*reinterpret_cast<__nv_bfloat162*>(&r3.y));
                float2 vc = __bfloat1622float2(*reinterpret_cast<__nv_bfloat162*>(&r3.z));
                float2 vd = __bfloat1622float2(*reinterpret_cast<__nv_bfloat162*>(&r3.w));
                c0 += va.x * p3; c1 += va.y * p3; c2 += vb.x * p3; c3 += vb.y * p3;
                c4 += vc.x * p3; c5 += vc.y * p3; c6 += vd.x * p3; c7 += vd.y * p3;
            }
            denom += (p0 + p1) + (p2 + p3);
        }
        for (; g < n_t; g++) {
            int s = __shfl_sync(0xffffffffu, myIdx, g);
            float e = __ldg(&g_ssrc1[s * HEADS + h]);
            uint4 r = *(const uint4*)&g_h1b[(size_t)s * D1 + ch];
            float p = __expf(lrelu(e + sdst_h));
            float2 va = __bfloat1622float2(*reinterpret_cast<__nv_bfloat162*>(&r.x));
            float2 vb = __bfloat1622float2(*reinterpret_cast<__nv_bfloat162*>(&r.y));
            float2 vc = __bfloat1622float2(*reinterpret_cast<__nv_bfloat162*>(&r.z));
            float2 vd = __bfloat1622float2(*reinterpret_cast<__nv_bfloat162*>(&r.w));
            c0 += va.x * p; c1 += va.y * p; c2 += vb.x * p; c3 += vb.y * p;
            c4 += vc.x * p; c5 += vc.y * p; c6 += vd.x * p; c7 += vd.y * p;
            denom += p;
        }
    }
    float inv = __frcp_rn(denom);
    float4 bb0 = *(const float4*)&b1[ch];
    float4 bb1 = *(const float4*)&b1[ch + 4];
    __nv_bfloat162 q0 = __floats2bfloat162_rn(fmaxf(c0 * inv + bb0.x, 0.f),
                                              fmaxf(c1 * inv + bb0.y, 0.f));
    __nv_bfloat162 q1 = __floats2bfloat162_rn(fmaxf(c2 * inv + bb0.z, 0.f),
                                              fmaxf(c3 * inv + bb0.w, 0.f));
    __nv_bfloat162 q2 = __floats2bfloat162_rn(fmaxf(c4 * inv + bb1.x, 0.f),
                                              fmaxf(c5 * inv + bb1.y, 0.f));
    __nv_bfloat162 q3 = __floats2bfloat162_rn(fmaxf(c6 * inv + bb1.z, 0.f),
                                              fmaxf(c7 * inv + bb1.w, 0.f));
    uint4 pk;
    pk.x = *reinterpret_cast<unsigned*>(&q0);
    pk.y = *reinterpret_cast<unsigned*>(&q1);
    pk.z = *reinterpret_cast<unsigned*>(&q2);
    pk.w = *reinterpret_cast<unsigned*>(&q3);
    *(uint4*)&g_h2b[nb] = pk;
}

// ======== GEMM2 via tf32 mma.sync (+ bf16 copy): h3 = h2b @ W2 =============
__global__ __launch_bounds__(256) void gemm2_tf32_kernel(const float* __restrict__ B, int M) {
    __shared__ unsigned As[128][36];
    __shared__ unsigned Bs[32][44];
    int tid = threadIdx.x;
    int warp = tid >> 5, lane = tid & 31;
    int q = lane >> 2, r4 = lane & 3;
    int rowBase = blockIdx.x * 128;
    int wm = warp * 16;

    float c[5][4] = {};
    for (int kc = 0; kc < 8; kc++) {
        for (int j = tid; j < 1024; j += 256) {
            int r = j >> 3;
            int k4 = (j & 7) * 4;
            int gr = rowBase + r;
            uint2 rv = make_uint2(0u, 0u);
            if (gr < M) rv = *(const uint2*)&g_h2b[(size_t)gr * D1 + kc * 32 + k4];
            uint4 t;
            t.x = rv.x << 16;
            t.y = rv.x & 0xffff0000u;
            t.z = rv.y << 16;
            t.w = rv.y & 0xffff0000u;
            *(uint4*)&As[r][k4] = t;
        }
        for (int j = tid; j < 1280; j += 256) {
            int k = j / NCLS;
            int n = j - k * NCLS;
            Bs[k][n] = f2tf32(B[(size_t)(kc * 32 + k) * NCLS + n]);
        }
        __syncthreads();
#pragma unroll
        for (int ks = 0; ks < 4; ks++) {
            int kk = ks * 8;
            unsigned a[4];
            int rr = wm + q;
            a[0] = As[rr][kk + r4];
            a[1] = As[rr + 8][kk + r4];
            a[2] = As[rr][kk + r4 + 4];
            a[3] = As[rr + 8][kk + r4 + 4];
#pragma unroll
            for (int nt = 0; nt < 5; nt++) {
                unsigned b0 = Bs[kk + r4][nt * 8 + q];
                unsigned b1 = Bs[kk + r4 + 4][nt * 8 + q];
                asm volatile(
                    "mma.sync.aligned.m16n8k8.row.col.f32.tf32.tf32.f32 "
                    "{%0,%1,%2,%3}, {%4,%5,%6,%7}, {%8,%9}, {%0,%1,%2,%3};"
                    : "+f"(c[nt][0]), "+f"(c[nt][1]), "+f"(c[nt][2]), "+f"(c[nt][3])
                    : "r"(a[0]), "r"(a[1]), "r"(a[2]), "r"(a[3]),
                      "r"(b0), "r"(b1));
            }
        }
        __syncthreads();
    }
    int r0 = rowBase + wm + q;
#pragma unroll
    for (int nt = 0; nt < 5; nt++) {
        int col = nt * 8 + r4 * 2;
        if (r0 < M) {
            float2 w0 = make_float2(c[nt][0], c[nt][1]);
            *(float2*)&g_h3[(size_t)r0 * NCLS + col] = w0;
            __nv_bfloat162 pb = __floats2bfloat162_rn(c[nt][0], c[nt][1]);
            *(unsigned*)&g_h3b[(size_t)r0 * NCLS + col] = *reinterpret_cast<unsigned*>(&pb);
        }
        if (r0 + 8 < M) {
            float2 w1 = make_float2(c[nt][2], c[nt][3]);
            *(float2*)&g_h3[(size_t)(r0 + 8) * NCLS + col] = w1;
            __nv_bfloat162 pb = __floats2bfloat162_rn(c[nt][2], c[nt][3]);
            *(unsigned*)&g_h3b[(size_t)(r0 + 8) * NCLS + col] = *reinterpret_cast<unsigned*>(&pb);
        }
    }
}

// ======== scores2: warp per node over h3 ====================================
__global__ __launch_bounds__(256) void scores2_kernel(const float* __restrict__ asrc,
                                                      const float* __restrict__ adst,
                                                      int n) {
    int wid  = (blockIdx.x * blockDim.x + threadIdx.x) >> 5;
    int lane = threadIdx.x & 31;
    if (wid >= n) return;
    size_t base = (size_t)wid * NCLS;
    float v0 = g_h3[base + lane];
    float v1 = (lane < 8) ? g_h3[base + 32 + lane] : 0.f;
    float a0 = asrc[lane], d0 = adst[lane];
    float a1 = (lane < 8) ? asrc[32 + lane] : 0.f;
    float d1 = (lane < 8) ? adst[32 + lane] : 0.f;
    float ps = v0 * a0 + v1 * a1;
    float pd = v0 * d0 + v1 * d1;
#pragma unroll
    for (int o = 16; o; o >>= 1) {
        ps += __shfl_xor_sync(0xffffffffu, ps, o);
        pd += __shfl_xor_sync(0xffffffffu, pd, o);
    }
    if (lane == 0) {
        g_ssrc2[wid] = ps;
        g_sdst2[wid] = pd;
        g_pself2[wid] = __expf(lrelu(ps + pd));
    }
}

// ======== aggregate2: warp/node, coop-index tiles, bf16 gather ==============
__global__ __launch_bounds__(256) void aggregate2_kernel(const float* __restrict__ b2,
                                                         float* __restrict__ out, int M) {
    int wid  = (blockIdx.x * blockDim.x + threadIdx.x) >> 5;
    int lane = threadIdx.x & 31;
    if (wid >= M) return;
    float sdst = g_sdst2[wid];
    float pself = g_pself2[wid];
    size_t nb = (size_t)wid * NCLS;
    bool act = lane < 20;
    int ch = lane * 2;
    float v0 = 0.f, v1 = 0.f;
    if (act) {
        float2 s = *(const float2*)&g_h3[nb + ch];
        v0 = s.x * pself; v1 = s.y * pself;
    }
    float denom = pself;
    int beg = g_rowptr[wid], end = g_rowptr[wid + 1];

    for (int tile = beg; tile < end; tile += 32) {
        int n_t = end - tile;
        if (n_t > 32) n_t = 32;
        int myIdx = 0;
        if (tile + lane < end) myIdx = g_csr_src[tile + lane];
        int g = 0;
        for (; g + 4 <= n_t; g += 4) {
            int s0 = __shfl_sync(0xffffffffu, myIdx, g);
            int s1 = __shfl_sync(0xffffffffu, myIdx, g + 1);
            int s2 = __shfl_sync(0xffffffffu, myIdx, g + 2);
            int s3 = __shfl_sync(0xffffffffu, myIdx, g + 3);
            float e0 = __ldg(&g_ssrc2[s0]);
            float e1 = __ldg(&g_ssrc2[s1]);
            float e2 = __ldg(&g_ssrc2[s2]);
            float e3 = __ldg(&g_ssrc2[s3]);
            unsigned r0 = 0, r1 = 0, r2 = 0, r3 = 0;
            if (act) {
                r0 = *(const unsigned*)&g_h3b[(size_t)s0 * NCLS + ch];
                r1 = *(const unsigned*)&g_h3b[(size_t)s1 * NCLS + ch];
                r2 = *(const unsigned*)&g_h3b[(size_t)s2 * NCLS + ch];
                r3 = *(const unsigned*)&g_h3b[(size_t)s3 * NCLS + ch];
            }
            float p0 = __expf(lrelu(e0 + sdst));
            float p1 = __expf(lrelu(e1 + sdst));
            float p2 = __expf(lrelu(e2 + sdst));
            float p3 = __expf(lrelu(e3 + sdst));
            float2 w0 = __bfloat1622float2(*reinterpret_cast<__nv_bfloat162*>(&r0));
            float2 w1 = __bfloat1622float2(*reinterpret_cast<__nv_bfloat162*>(&r1));
            float2 w2 = __bfloat1622float2(*reinterpret_cast<__nv_bfloat162*>(&r2));
            float2 w3 = __bfloat1622float2(*reinterpret_cast<__nv_bfloat162*>(&r3));
            v0 += w0.x * p0 + w1.x * p1 + w2.x * p2 + w3.x * p3;
            v1 += w0.y * p0 + w1.y * p1 + w2.y * p2 + w3.y * p3;
            denom += (p0 + p1) + (p2 + p3);
        }
        for (; g < n_t; g++) {
            int s = __shfl_sync(0xffffffffu, myIdx, g);
            float e = __ldg(&g_ssrc2[s]);
            unsigned r = 0;
            if (act) r = *(const unsigned*)&g_h3b[(size_t)s * NCLS + ch];
            float p = __expf(lrelu(e + sdst));
            float2 w = __bfloat1622float2(*reinterpret_cast<__nv_bfloat162*>(&r));
            v0 += w.x * p; v1 += w.y * p;
            denom += p;
        }
    }
    float inv = __frcp_rn(denom);
    float z0 = -FLT_MAX, z1 = -FLT_MAX;
    if (act) {
        z0 = v0 * inv + b2[ch];
        z1 = v1 * inv + b2[ch + 1];
    }
    float m = fmaxf(z0, z1);
#pragma unroll
    for (int o = 16; o; o >>= 1) m = fmaxf(m, __shfl_xor_sync(0xffffffffu, m, o));
    float s = act ? (expf(z0 - m) + expf(z1 - m)) : 0.f;
#pragma unroll
    for (int o = 16; o; o >>= 1) s += __shfl_xor_sync(0xffffffffu, s, o);
    float ls = logf(s);
    if (act) {
        out[nb + ch]     = z0 - m - ls;
        out[nb + ch + 1] = z1 - m - ls;
    }
}

// ---------------------------------------------------------------------------
extern "C" void kernel_launch(void* const* d_in, const int* in_sizes, int n_in,
                              void* d_out, int out_size) {
    const float* x     = (const float*)d_in[0];
    const int*   ei    = (const int*)d_in[1];      // JAX x64 disabled -> int32
    const float* W1    = (const float*)d_in[2];
    const float* asrc1 = (const float*)d_in[3];
    const float* adst1 = (const float*)d_in[4];
    const float* b1    = (const float*)d_in[5];
    const float* W2    = (const float*)d_in[6];
    const float* asrc2 = (const float*)d_in[7];
    const float* adst2 = (const float*)d_in[8];
    const float* b2    = (const float*)d_in[9];
    float* out = (float*)d_out;

    int M = in_sizes[0] / F_IN;        // 100000
    int E = in_sizes[1] / 2;           // 1600000
    const int* src = ei;
    const int* dst = ei + E;
    int NB = (M + SCAN_B - 1) / SCAN_B;

    static cudaStream_t s2 = nullptr;
    static cudaEvent_t evFork = nullptr, evJoin = nullptr;
    if (s2 == nullptr) {
        cudaStreamCreateWithFlags(&s2, cudaStreamNonBlocking);
        cudaEventCreateWithFlags(&evFork, cudaEventDisableTiming);
        cudaEventCreateWithFlags(&evJoin, cudaEventDisableTiming);
    }

    // Fork: CSR build on s2, GEMM1 (with fused scores) on main stream.
    cudaEventRecord(evFork, 0);
    cudaStreamWaitEvent(s2, evFork, 0);

    zero_counts_kernel<<<(M + 255) / 256, 256, 0, s2>>>(M);
    hist_kernel<<<(E + 255) / 256, 256, 0, s2>>>(dst, E);
    scan_sums_kernel<<<NB, SCAN_B, 0, s2>>>(M);
    scan_offsets_kernel<<<1, SCAN_B, 0, s2>>>(NB, M);
    scan_apply_kernel<<<NB, SCAN_B, 0, s2>>>(M);
    scatter_kernel<<<(E + 255) / 256, 256, 0, s2>>>(src, dst, E);
    cudaEventRecord(evJoin, s2);

    {
        dim3 grid(D1 / 64, (M + 63) / 64);
        gemm1_tf32_kernel<<<grid, 256>>>(x, W1, asrc1, adst1, M);
    }

    cudaStreamWaitEvent(0, evJoin, 0);

    aggregate1_kernel<<<(M * 32 + 255) / 256, 256>>>(b1, M);

    // Layer 2
    gemm2_tf32_kernel<<<(M + 127) / 128, 256>>>(W2, M);
    scores2_kernel<<<(M * 32 + 255) / 256, 256>>>(asrc2, adst2, M);
    aggregate2_kernel<<<(M * 32 + 255) / 256, 256>>>(b2, out, M);
}